// round 1
// baseline (speedup 1.0000x reference)
#include <cuda_runtime.h>
#include <math.h>

#define B_    8
#define N_    10000
#define D_    16
#define E_    320000
#define EH_   32
#define EOUT_ 30
#define NOUT_ 64

// ---------------- device scratch (no allocations allowed) ----------------
__device__ double g_stats[4];                 // sum0, sum1, sumsq0, sumsq1
__device__ float  g_norm[4];                  // mean0, mean1, rstd0, rstd1
__device__ float  g_agg[B_ * N_ * EOUT_];     // 9.6 MB aggregate buffer

__device__ __forceinline__ float sigmoidf(float v) {
    return 1.0f / (1.0f + __expf(-v));
}

// ---------------- zero scratch ----------------
__global__ void zero_kernel() {
    const int total = B_ * N_ * EOUT_;
    for (int i = blockIdx.x * blockDim.x + threadIdx.x; i < total;
         i += gridDim.x * blockDim.x) {
        g_agg[i] = 0.0f;
    }
    if (blockIdx.x == 0 && threadIdx.x < 4) g_stats[threadIdx.x] = 0.0;
}

// ---------------- edge_attr mean/std reduction (double precision) ----------------
__global__ void stats_kernel(const float* __restrict__ ea) {
    double s0 = 0.0, s1 = 0.0, q0 = 0.0, q1 = 0.0;
    for (int i = blockIdx.x * blockDim.x + threadIdx.x; i < E_;
         i += gridDim.x * blockDim.x) {
        float a = ea[2 * i];
        float b = ea[2 * i + 1];
        s0 += (double)a;
        s1 += (double)b;
        q0 += (double)a * (double)a;
        q1 += (double)b * (double)b;
    }
    for (int o = 16; o > 0; o >>= 1) {
        s0 += __shfl_down_sync(0xffffffffu, s0, o);
        s1 += __shfl_down_sync(0xffffffffu, s1, o);
        q0 += __shfl_down_sync(0xffffffffu, q0, o);
        q1 += __shfl_down_sync(0xffffffffu, q1, o);
    }
    if ((threadIdx.x & 31) == 0) {
        atomicAdd(&g_stats[0], s0);
        atomicAdd(&g_stats[1], s1);
        atomicAdd(&g_stats[2], q0);
        atomicAdd(&g_stats[3], q1);
    }
}

__global__ void finalize_kernel() {
    if (threadIdx.x == 0 && blockIdx.x == 0) {
        const double n = (double)E_;
        double m0 = g_stats[0] / n;
        double m1 = g_stats[1] / n;
        double v0 = (g_stats[2] - g_stats[0] * g_stats[0] / n) / (n - 1.0);
        double v1 = (g_stats[3] - g_stats[1] * g_stats[1] / n) / (n - 1.0);
        g_norm[0] = (float)m0;
        g_norm[1] = (float)m1;
        g_norm[2] = (float)(1.0 / sqrt(v0));
        g_norm[3] = (float)(1.0 / sqrt(v1));
    }
}

// ---------------- edge MLP + scatter ----------------
__device__ __forceinline__ void acc_row(float (&h)[EH_], const float* wrow, float f) {
#pragma unroll
    for (int jj = 0; jj < 8; jj++) {
        float4 v = ((const float4*)wrow)[jj];
        h[4 * jj + 0] = fmaf(f, v.x, h[4 * jj + 0]);
        h[4 * jj + 1] = fmaf(f, v.y, h[4 * jj + 1]);
        h[4 * jj + 2] = fmaf(f, v.z, h[4 * jj + 2]);
        h[4 * jj + 3] = fmaf(f, v.w, h[4 * jj + 3]);
    }
}

__global__ void __launch_bounds__(256) edge_kernel(
    const float* __restrict__ x, const int* __restrict__ ei,
    const float* __restrict__ ea,
    const float* __restrict__ wm, const float* __restrict__ ws,
    const float* __restrict__ W1, const float* __restrict__ b1,
    const float* __restrict__ W2, const float* __restrict__ b2)
{
    __shared__ __align__(16) float sW1[35 * EH_];       // [35][32]
    __shared__ __align__(16) float sW2t[EOUT_ * EH_];   // transposed [30][32]
    __shared__ float sb1[EH_];
    __shared__ float sb2[EOUT_];

    for (int i = threadIdx.x; i < 35 * EH_; i += blockDim.x) sW1[i] = W1[i];
    for (int i = threadIdx.x; i < EH_ * EOUT_; i += blockDim.x) {
        int j = i / EOUT_;
        int c = i % EOUT_;
        sW2t[c * EH_ + j] = W2[i];
    }
    if (threadIdx.x < EH_)   sb1[threadIdx.x] = b1[threadIdx.x];
    if (threadIdx.x < EOUT_) sb2[threadIdx.x] = b2[threadIdx.x];
    __syncthreads();

    unsigned gid = blockIdx.x * blockDim.x + threadIdx.x;
    if (gid >= (unsigned)(E_) * B_) return;
    int e = gid >> 3;       // edge id
    int b = gid & 7;        // batch id
    int src = ei[e];
    int tgt = ei[E_ + e];

    float xs[D_], xt[D_];
    const float4* ps = (const float4*)(x + (b * N_ + src) * D_);
    const float4* pt = (const float4*)(x + (b * N_ + tgt) * D_);
#pragma unroll
    for (int q = 0; q < 4; q++) {
        float4 v = ps[q];
        xs[4 * q + 0] = v.x; xs[4 * q + 1] = v.y;
        xs[4 * q + 2] = v.z; xs[4 * q + 3] = v.w;
        float4 w = pt[q];
        xt[4 * q + 0] = w.x; xt[4 * q + 1] = w.y;
        xt[4 * q + 2] = w.z; xt[4 * q + 3] = w.w;
    }

    float speed = fmaf(xs[14], ws[0], wm[0]);
    float dir   = fmaf(xs[15], ws[1], wm[1]);
    float cd    = ea[2 * e];
    float cdi   = ea[2 * e + 1];
    float theta = fabsf(cdi - dir);
    float ewt   = fmaxf(0.0f, 3.0f * speed * cosf(theta) / cd);
    float ean0  = (cd  - g_norm[0]) * g_norm[2];
    float ean1  = (cdi - g_norm[1]) * g_norm[3];

    float h[EH_];
#pragma unroll
    for (int j = 0; j < EH_; j++) h[j] = sb1[j];

#pragma unroll
    for (int k = 0; k < D_; k++) acc_row(h, sW1 + k * EH_, xs[k]);
#pragma unroll
    for (int k = 0; k < D_; k++) acc_row(h, sW1 + (D_ + k) * EH_, xt[k]);
    acc_row(h, sW1 + 32 * EH_, ean0);
    acc_row(h, sW1 + 33 * EH_, ean1);
    acc_row(h, sW1 + 34 * EH_, ewt);

#pragma unroll
    for (int j = 0; j < EH_; j++) h[j] = sigmoidf(h[j]);

    float* at = g_agg + (b * N_ + tgt) * EOUT_;
    float* as = g_agg + (b * N_ + src) * EOUT_;
#pragma unroll 6
    for (int i = 0; i < EOUT_; i++) {
        float acc = sb2[i];
        const float4* wr = (const float4*)(sW2t + i * EH_);
#pragma unroll
        for (int jj = 0; jj < 8; jj++) {
            float4 v = wr[jj];
            acc = fmaf(h[4 * jj + 0], v.x, acc);
            acc = fmaf(h[4 * jj + 1], v.y, acc);
            acc = fmaf(h[4 * jj + 2], v.z, acc);
            acc = fmaf(h[4 * jj + 3], v.w, acc);
        }
        float ev = sigmoidf(acc);
        atomicAdd(at + i, ev);
        atomicAdd(as + i, -ev);
    }
}

// ---------------- node MLP ----------------
__global__ void __launch_bounds__(256) node_kernel(
    const float* __restrict__ Wn, const float* __restrict__ bn,
    float* __restrict__ out)
{
    __shared__ __align__(16) float sWn[EOUT_ * NOUT_];
    __shared__ float sbn[NOUT_];
    for (int i = threadIdx.x; i < EOUT_ * NOUT_; i += blockDim.x) sWn[i] = Wn[i];
    if (threadIdx.x < NOUT_) sbn[threadIdx.x] = bn[threadIdx.x];
    __syncthreads();

    int node = blockIdx.x * blockDim.x + threadIdx.x;  // flattened (b, n)
    if (node >= B_ * N_) return;

    float a[EOUT_];
    const float* ag = g_agg + node * EOUT_;
#pragma unroll
    for (int j = 0; j < EOUT_; j++) a[j] = ag[j];

    float* op = out + (size_t)node * NOUT_;
#pragma unroll
    for (int o = 0; o < NOUT_; o += 8) {
        float acc[8];
#pragma unroll
        for (int t = 0; t < 8; t++) acc[t] = sbn[o + t];
#pragma unroll
        for (int j = 0; j < EOUT_; j++) {
            float4 w0 = *(const float4*)(sWn + j * NOUT_ + o);
            float4 w1 = *(const float4*)(sWn + j * NOUT_ + o + 4);
            acc[0] = fmaf(a[j], w0.x, acc[0]);
            acc[1] = fmaf(a[j], w0.y, acc[1]);
            acc[2] = fmaf(a[j], w0.z, acc[2]);
            acc[3] = fmaf(a[j], w0.w, acc[3]);
            acc[4] = fmaf(a[j], w1.x, acc[4]);
            acc[5] = fmaf(a[j], w1.y, acc[5]);
            acc[6] = fmaf(a[j], w1.z, acc[6]);
            acc[7] = fmaf(a[j], w1.w, acc[7]);
        }
        float4 r0 = make_float4(sigmoidf(acc[0]), sigmoidf(acc[1]),
                                sigmoidf(acc[2]), sigmoidf(acc[3]));
        float4 r1 = make_float4(sigmoidf(acc[4]), sigmoidf(acc[5]),
                                sigmoidf(acc[6]), sigmoidf(acc[7]));
        *(float4*)(op + o)     = r0;
        *(float4*)(op + o + 4) = r1;
    }
}

// ---------------- launch ----------------
extern "C" void kernel_launch(void* const* d_in, const int* in_sizes, int n_in,
                              void* d_out, int out_size) {
    const float* x  = (const float*)d_in[0];
    const int*   ei = (const int*)d_in[1];
    const float* ea = (const float*)d_in[2];
    const float* wm = (const float*)d_in[3];
    const float* ws = (const float*)d_in[4];
    const float* W1 = (const float*)d_in[5];
    const float* b1 = (const float*)d_in[6];
    const float* W2 = (const float*)d_in[7];
    const float* b2 = (const float*)d_in[8];
    const float* Wn = (const float*)d_in[9];
    const float* bn = (const float*)d_in[10];
    float* out = (float*)d_out;

    zero_kernel<<<512, 256>>>();
    stats_kernel<<<256, 256>>>(ea);
    finalize_kernel<<<1, 32>>>();
    edge_kernel<<<(E_ * B_) / 256, 256>>>(x, ei, ea, wm, ws, W1, b1, W2, b2);
    node_kernel<<<(B_ * N_ + 255) / 256, 256>>>(Wn, bn, out);
}

// round 2
// speedup vs baseline: 1.4144x; 1.4144x over previous
#include <cuda_runtime.h>
#include <math.h>

#define B_     8
#define N_     10000
#define D_     16
#define E_     320000
#define EH_    32
#define EOUT_  30
#define EOUTP_ 32   // padded agg row (128B-aligned for v4 reductions)
#define NOUT_  64

// ---------------- device scratch (no allocations allowed) ----------------
__device__ double g_stats[4];                        // sum0, sum1, sumsq0, sumsq1
__device__ float  g_norm[4];                         // mean0, mean1, rstd0, rstd1
__device__ __align__(16) float g_agg[B_ * N_ * EOUTP_];  // 10.24 MB padded agg

__device__ __forceinline__ float sigmoidf(float v) {
    return 1.0f / (1.0f + __expf(-v));
}

__device__ __forceinline__ void red_v4(float* p, float a, float b, float c, float d) {
    asm volatile("red.global.add.v4.f32 [%0], {%1, %2, %3, %4};"
                 :: "l"(p), "f"(a), "f"(b), "f"(c), "f"(d) : "memory");
}
__device__ __forceinline__ void red_v2(float* p, float a, float b) {
    asm volatile("red.global.add.v2.f32 [%0], {%1, %2};"
                 :: "l"(p), "f"(a), "f"(b) : "memory");
}

// ---------------- zero scratch ----------------
__global__ void zero_kernel() {
    const int total4 = (B_ * N_ * EOUTP_) / 4;
    float4 z = make_float4(0.f, 0.f, 0.f, 0.f);
    for (int i = blockIdx.x * blockDim.x + threadIdx.x; i < total4;
         i += gridDim.x * blockDim.x) {
        ((float4*)g_agg)[i] = z;
    }
    if (blockIdx.x == 0 && threadIdx.x < 4) g_stats[threadIdx.x] = 0.0;
}

// ---------------- edge_attr mean/std reduction (double precision) ----------------
__global__ void stats_kernel(const float* __restrict__ ea) {
    double s0 = 0.0, s1 = 0.0, q0 = 0.0, q1 = 0.0;
    for (int i = blockIdx.x * blockDim.x + threadIdx.x; i < E_;
         i += gridDim.x * blockDim.x) {
        float a = ea[2 * i];
        float b = ea[2 * i + 1];
        s0 += (double)a;
        s1 += (double)b;
        q0 += (double)a * (double)a;
        q1 += (double)b * (double)b;
    }
    for (int o = 16; o > 0; o >>= 1) {
        s0 += __shfl_down_sync(0xffffffffu, s0, o);
        s1 += __shfl_down_sync(0xffffffffu, s1, o);
        q0 += __shfl_down_sync(0xffffffffu, q0, o);
        q1 += __shfl_down_sync(0xffffffffu, q1, o);
    }
    if ((threadIdx.x & 31) == 0) {
        atomicAdd(&g_stats[0], s0);
        atomicAdd(&g_stats[1], s1);
        atomicAdd(&g_stats[2], q0);
        atomicAdd(&g_stats[3], q1);
    }
}

__global__ void finalize_kernel() {
    if (threadIdx.x == 0 && blockIdx.x == 0) {
        const double n = (double)E_;
        double v0 = (g_stats[2] - g_stats[0] * g_stats[0] / n) / (n - 1.0);
        double v1 = (g_stats[3] - g_stats[1] * g_stats[1] / n) / (n - 1.0);
        g_norm[0] = (float)(g_stats[0] / n);
        g_norm[1] = (float)(g_stats[1] / n);
        g_norm[2] = (float)(1.0 / sqrt(v0));
        g_norm[3] = (float)(1.0 / sqrt(v1));
    }
}

// ---------------- edge MLP + scatter ----------------
__device__ __forceinline__ void acc_row(float (&h)[EH_], const float* wrow, float f) {
#pragma unroll
    for (int jj = 0; jj < 8; jj++) {
        float4 v = ((const float4*)wrow)[jj];
        h[4 * jj + 0] = fmaf(f, v.x, h[4 * jj + 0]);
        h[4 * jj + 1] = fmaf(f, v.y, h[4 * jj + 1]);
        h[4 * jj + 2] = fmaf(f, v.z, h[4 * jj + 2]);
        h[4 * jj + 3] = fmaf(f, v.w, h[4 * jj + 3]);
    }
}

__device__ __forceinline__ float dot32(const float (&h)[EH_], const float* wrow) {
    float acc = 0.0f;
#pragma unroll
    for (int jj = 0; jj < 8; jj++) {
        float4 v = ((const float4*)wrow)[jj];
        acc = fmaf(h[4 * jj + 0], v.x, acc);
        acc = fmaf(h[4 * jj + 1], v.y, acc);
        acc = fmaf(h[4 * jj + 2], v.z, acc);
        acc = fmaf(h[4 * jj + 3], v.w, acc);
    }
    return acc;
}

__global__ void __launch_bounds__(256) edge_kernel(
    const float* __restrict__ x, const int* __restrict__ ei,
    const float* __restrict__ ea,
    const float* __restrict__ wm, const float* __restrict__ ws,
    const float* __restrict__ W1, const float* __restrict__ b1,
    const float* __restrict__ W2, const float* __restrict__ b2)
{
    __shared__ __align__(16) float sW1[35 * EH_];       // [35][32]
    __shared__ __align__(16) float sW2t[EOUT_ * EH_];   // transposed [30][32]
    __shared__ float sb1[EH_];
    __shared__ float sb2[EOUT_];

    for (int i = threadIdx.x; i < 35 * EH_; i += blockDim.x) sW1[i] = W1[i];
    for (int i = threadIdx.x; i < EH_ * EOUT_; i += blockDim.x) {
        int j = i / EOUT_;
        int c = i % EOUT_;
        sW2t[c * EH_ + j] = W2[i];
    }
    if (threadIdx.x < EH_)   sb1[threadIdx.x] = b1[threadIdx.x];
    if (threadIdx.x < EOUT_) sb2[threadIdx.x] = b2[threadIdx.x];
    __syncthreads();

    unsigned gid = blockIdx.x * blockDim.x + threadIdx.x;
    if (gid >= (unsigned)(E_) * B_) return;
    int e = gid >> 3;       // edge id
    int b = gid & 7;        // batch id
    int src = ei[e];
    int tgt = ei[E_ + e];

    float xs[D_], xt[D_];
    const float4* ps = (const float4*)(x + (b * N_ + src) * D_);
    const float4* pt = (const float4*)(x + (b * N_ + tgt) * D_);
#pragma unroll
    for (int q = 0; q < 4; q++) {
        float4 v = ps[q];
        xs[4 * q + 0] = v.x; xs[4 * q + 1] = v.y;
        xs[4 * q + 2] = v.z; xs[4 * q + 3] = v.w;
        float4 w = pt[q];
        xt[4 * q + 0] = w.x; xt[4 * q + 1] = w.y;
        xt[4 * q + 2] = w.z; xt[4 * q + 3] = w.w;
    }

    float speed = fmaf(xs[14], ws[0], wm[0]);
    float dir   = fmaf(xs[15], ws[1], wm[1]);
    float cd    = ea[2 * e];
    float cdi   = ea[2 * e + 1];
    float theta = fabsf(cdi - dir);
    float ewt   = fmaxf(0.0f, 3.0f * speed * __cosf(theta) / cd);
    float ean0  = (cd  - g_norm[0]) * g_norm[2];
    float ean1  = (cdi - g_norm[1]) * g_norm[3];

    float h[EH_];
#pragma unroll
    for (int j = 0; j < EH_; j++) h[j] = sb1[j];

#pragma unroll
    for (int k = 0; k < D_; k++) acc_row(h, sW1 + k * EH_, xs[k]);
#pragma unroll
    for (int k = 0; k < D_; k++) acc_row(h, sW1 + (D_ + k) * EH_, xt[k]);
    acc_row(h, sW1 + 32 * EH_, ean0);
    acc_row(h, sW1 + 33 * EH_, ean1);
    acc_row(h, sW1 + 34 * EH_, ewt);

#pragma unroll
    for (int j = 0; j < EH_; j++) h[j] = sigmoidf(h[j]);

    float* at = g_agg + (size_t)(b * N_ + tgt) * EOUTP_;
    float* as = g_agg + (size_t)(b * N_ + src) * EOUTP_;

    // 7 chunks of 4 outputs, vector reductions (28 outputs)
#pragma unroll
    for (int c4 = 0; c4 < 7; c4++) {
        int i0 = 4 * c4;
        float e0 = sigmoidf(sb2[i0 + 0] + dot32(h, sW2t + (i0 + 0) * EH_));
        float e1 = sigmoidf(sb2[i0 + 1] + dot32(h, sW2t + (i0 + 1) * EH_));
        float e2 = sigmoidf(sb2[i0 + 2] + dot32(h, sW2t + (i0 + 2) * EH_));
        float e3 = sigmoidf(sb2[i0 + 3] + dot32(h, sW2t + (i0 + 3) * EH_));
        red_v4(at + i0,  e0,  e1,  e2,  e3);
        red_v4(as + i0, -e0, -e1, -e2, -e3);
    }
    // last 2 outputs (28, 29): v2 at 8B-aligned offset 112
    {
        float e0 = sigmoidf(sb2[28] + dot32(h, sW2t + 28 * EH_));
        float e1 = sigmoidf(sb2[29] + dot32(h, sW2t + 29 * EH_));
        red_v2(at + 28,  e0,  e1);
        red_v2(as + 28, -e0, -e1);
    }
}

// ---------------- node MLP ----------------
__global__ void __launch_bounds__(256) node_kernel(
    const float* __restrict__ Wn, const float* __restrict__ bn,
    float* __restrict__ out)
{
    __shared__ __align__(16) float sWn[EOUT_ * NOUT_];
    __shared__ float sbn[NOUT_];
    for (int i = threadIdx.x; i < EOUT_ * NOUT_; i += blockDim.x) sWn[i] = Wn[i];
    if (threadIdx.x < NOUT_) sbn[threadIdx.x] = bn[threadIdx.x];
    __syncthreads();

    int node = blockIdx.x * blockDim.x + threadIdx.x;  // flattened (b, n)
    if (node >= B_ * N_) return;

    float a[EOUT_];
    const float4* ag = (const float4*)(g_agg + (size_t)node * EOUTP_);
#pragma unroll
    for (int q = 0; q < 7; q++) {
        float4 v = ag[q];
        a[4 * q + 0] = v.x; a[4 * q + 1] = v.y;
        a[4 * q + 2] = v.z; a[4 * q + 3] = v.w;
    }
    {
        float4 v = ag[7];
        a[28] = v.x; a[29] = v.y;  // ignore padding .z/.w
    }

    float* op = out + (size_t)node * NOUT_;
#pragma unroll
    for (int o = 0; o < NOUT_; o += 8) {
        float acc[8];
#pragma unroll
        for (int t = 0; t < 8; t++) acc[t] = sbn[o + t];
#pragma unroll
        for (int j = 0; j < EOUT_; j++) {
            float4 w0 = *(const float4*)(sWn + j * NOUT_ + o);
            float4 w1 = *(const float4*)(sWn + j * NOUT_ + o + 4);
            acc[0] = fmaf(a[j], w0.x, acc[0]);
            acc[1] = fmaf(a[j], w0.y, acc[1]);
            acc[2] = fmaf(a[j], w0.z, acc[2]);
            acc[3] = fmaf(a[j], w0.w, acc[3]);
            acc[4] = fmaf(a[j], w1.x, acc[4]);
            acc[5] = fmaf(a[j], w1.y, acc[5]);
            acc[6] = fmaf(a[j], w1.z, acc[6]);
            acc[7] = fmaf(a[j], w1.w, acc[7]);
        }
        float4 r0 = make_float4(sigmoidf(acc[0]), sigmoidf(acc[1]),
                                sigmoidf(acc[2]), sigmoidf(acc[3]));
        float4 r1 = make_float4(sigmoidf(acc[4]), sigmoidf(acc[5]),
                                sigmoidf(acc[6]), sigmoidf(acc[7]));
        *(float4*)(op + o)     = r0;
        *(float4*)(op + o + 4) = r1;
    }
}

// ---------------- launch ----------------
extern "C" void kernel_launch(void* const* d_in, const int* in_sizes, int n_in,
                              void* d_out, int out_size) {
    const float* x  = (const float*)d_in[0];
    const int*   ei = (const int*)d_in[1];
    const float* ea = (const float*)d_in[2];
    const float* wm = (const float*)d_in[3];
    const float* ws = (const float*)d_in[4];
    const float* W1 = (const float*)d_in[5];
    const float* b1 = (const float*)d_in[6];
    const float* W2 = (const float*)d_in[7];
    const float* b2 = (const float*)d_in[8];
    const float* Wn = (const float*)d_in[9];
    const float* bn = (const float*)d_in[10];
    float* out = (float*)d_out;

    zero_kernel<<<512, 256>>>();
    stats_kernel<<<256, 256>>>(ea);
    finalize_kernel<<<1, 32>>>();
    edge_kernel<<<(E_ * B_) / 256, 256>>>(x, ei, ea, wm, ws, W1, b1, W2, b2);
    node_kernel<<<(B_ * N_ + 255) / 256, 256>>>(Wn, bn, out);
}